// round 10
// baseline (speedup 1.0000x reference)
#include <cuda_runtime.h>
#include <mma.h>
#include <cstdint>

using namespace nvcuda;

// Shapes
#define B_  4
#define S_  1024
#define D_  2048
#define H_  16
#define HD_ 128
#define RD_ 64
#define NT  (B_*S_)      // 4096 tokens
#define D3  (3*D_)       // 6144
#define KC  8            // mod-gemm split-K chunks

// ---------------- scratch (static device arrays; allocation-free) -------------
__device__ float g_m3p[KC*B_*D3];
__device__ float g_m3[B_*D3];
__device__ float g_xn[NT*D_];
__device__ float g_qkv[(size_t)NT*D3];
__device__ float g_q[(size_t)B_*H_*S_*HD_];
__device__ float g_k[(size_t)B_*H_*S_*HD_];
__device__ float g_v[(size_t)B_*H_*S_*HD_];
__device__ float g_s[(size_t)B_*H_*S_*S_];   // 256 MB scores
__device__ float g_o[(size_t)NT*D_];
__device__ float g_t[(size_t)NT*D_];
__device__ float g_qkvw[(size_t)D_*D3];      // tf32-rounded qkv_w
__device__ float g_outw[(size_t)D_*D_];      // tf32-rounded out_w

// ---------------- tf32 round-to-nearest helper --------------------------------
__device__ __forceinline__ float rtf32(float x) {
    float r;
    asm("cvt.rna.tf32.f32 %0, %1;" : "=f"(r) : "f"(x));
    return r;
}

// ---------------- cp.async helpers -------------------------------------------
__device__ __forceinline__ void cp_async16(void* smem_dst, const void* gmem_src) {
    uint32_t s = (uint32_t)__cvta_generic_to_shared(smem_dst);
    asm volatile("cp.async.cg.shared.global [%0], [%1], 16;\n" :: "r"(s), "l"(gmem_src));
}
__device__ __forceinline__ void cp_commit() {
    asm volatile("cp.async.commit_group;\n" ::: "memory");
}
__device__ __forceinline__ void cp_wait1() {
    asm volatile("cp.async.wait_group 1;\n" ::: "memory");
}

// ---------------- helpers ----------------------------------------------------
template<int NW>
__device__ __forceinline__ float block_sum(float v, float* sh) {
    #pragma unroll
    for (int o = 16; o > 0; o >>= 1) v += __shfl_xor_sync(0xffffffffu, v, o);
    int w = threadIdx.x >> 5;
    if ((threadIdx.x & 31) == 0) sh[w] = v;
    __syncthreads();
    float r = 0.f;
    #pragma unroll
    for (int i = 0; i < NW; i++) r += sh[i];
    __syncthreads();
    return r;
}

// ---------------- K0: tf32-round weights to scratch ---------------------------
__global__ void k_round(const float* __restrict__ in, float* __restrict__ o) {
    int i = blockIdx.x * 256 + threadIdx.x;
    float4 v = reinterpret_cast<const float4*>(in)[i];
    v.x = rtf32(v.x); v.y = rtf32(v.y); v.z = rtf32(v.z); v.w = rtf32(v.w);
    reinterpret_cast<float4*>(o)[i] = v;
}

// ---------------- K1: mod GEMM (split-K partials, deterministic) --------------
__global__ void k_mod_part(const float* __restrict__ mod,
                           const float* __restrict__ mod_w) {
    __shared__ float sm[B_*256];
    int kc = blockIdx.y;
    int k0 = kc * 256;
    for (int i = threadIdx.x; i < B_*256; i += blockDim.x)
        sm[i] = mod[(i >> 8) * D_ + k0 + (i & 255)];
    __syncthreads();
    int j = blockIdx.x * 128 + threadIdx.x;
    float a0=0.f, a1=0.f, a2=0.f, a3=0.f;
    #pragma unroll 4
    for (int k = 0; k < 256; k++) {
        float w = mod_w[(size_t)(k0 + k) * D3 + j];
        a0 = fmaf(sm[k],       w, a0);
        a1 = fmaf(sm[256 + k], w, a1);
        a2 = fmaf(sm[512 + k], w, a2);
        a3 = fmaf(sm[768 + k], w, a3);
    }
    float* p = g_m3p + (size_t)kc * (B_*D3);
    p[0*D3 + j] = a0; p[1*D3 + j] = a1; p[2*D3 + j] = a2; p[3*D3 + j] = a3;
}

__global__ void k_mod_red(const float* __restrict__ mod_b) {
    int i = blockIdx.x * 256 + threadIdx.x;   // 0 .. B_*D3-1
    float s = 0.f;
    #pragma unroll
    for (int c = 0; c < KC; c++) s += g_m3p[c * (B_*D3) + i];
    g_m3[i] = s + mod_b[i % D3];
}

// ---------------- K2: LayerNorm + AdaLN modulation (tf32-rounded out) ---------
__global__ void k_lnmod(const float* __restrict__ x) {
    __shared__ float sh[8];
    int m = blockIdx.x;       // token
    int b = m >> 10;
    int t = threadIdx.x;
    const float* xr = x + (size_t)m * D_;
    float4 v0 = *reinterpret_cast<const float4*>(xr + t*4);
    float4 v1 = *reinterpret_cast<const float4*>(xr + 1024 + t*4);
    float s = v0.x+v0.y+v0.z+v0.w + v1.x+v1.y+v1.z+v1.w;
    s = block_sum<8>(s, sh);
    float mean = s * (1.f / D_);
    float d0=v0.x-mean, d1=v0.y-mean, d2=v0.z-mean, d3=v0.w-mean;
    float d4=v1.x-mean, d5=v1.y-mean, d6=v1.z-mean, d7=v1.w-mean;
    float ss = d0*d0+d1*d1+d2*d2+d3*d3+d4*d4+d5*d5+d6*d6+d7*d7;
    ss = block_sum<8>(ss, sh);
    float rinv = rsqrtf(ss * (1.f / D_) + 1e-6f);
    const float* mb  = g_m3 + b * D3;        // bias
    const float* msc = mb + D_;              // scale
    int e0 = t*4, e1 = 1024 + t*4;
    float4 o0, o1;
    o0.x = rtf32(d0*rinv*(1.f+msc[e0+0]) + mb[e0+0]);
    o0.y = rtf32(d1*rinv*(1.f+msc[e0+1]) + mb[e0+1]);
    o0.z = rtf32(d2*rinv*(1.f+msc[e0+2]) + mb[e0+2]);
    o0.w = rtf32(d3*rinv*(1.f+msc[e0+3]) + mb[e0+3]);
    o1.x = rtf32(d4*rinv*(1.f+msc[e1+0]) + mb[e1+0]);
    o1.y = rtf32(d5*rinv*(1.f+msc[e1+1]) + mb[e1+1]);
    o1.z = rtf32(d6*rinv*(1.f+msc[e1+2]) + mb[e1+2]);
    o1.w = rtf32(d7*rinv*(1.f+msc[e1+3]) + mb[e1+3]);
    float* xo = g_xn + (size_t)m * D_;
    *reinterpret_cast<float4*>(xo + e0) = o0;
    *reinterpret_cast<float4*>(xo + e1) = o1;
}

// ---------------- tf32 WMMA GEMM, 2-stage, pad-4, 3 CTAs/SM -------------------
// C[M,N] = A[M,K] * B[K,N]; 128x128 tile, 4 warps of 64x64, BK=32.
template<bool RND>
__global__ void __launch_bounds__(128, 3)
k_gemm(const float* __restrict__ A, int lda, long long sA1, long long sA2,
       const float* __restrict__ B, int ldb, long long sB1, long long sB2,
       float*       __restrict__ C, int ldc, long long sC1, long long sC2,
       int K, int zdiv) {
    constexpr int BM = 128, BN = 128, BK = 32;
    constexpr int AKP = BK + 4;    // 36 floats/row (144 B, 16B-mult)
    constexpr int BNP = BN + 4;    // 132 floats/row (528 B)
    constexpr int AS_SZ = BM * AKP;    // 4608
    constexpr int BS_SZ = BK * BNP;    // 4224
    extern __shared__ __align__(16) float smem[];
    float* As0 = smem;
    float* As1 = smem + AS_SZ;
    float* Bs0 = smem + 2 * AS_SZ;
    float* Bs1 = smem + 2 * AS_SZ + BS_SZ;

    int z  = blockIdx.z;
    int z1 = z / zdiv, z2 = z - z1 * zdiv;
    A += (size_t)(z1 * sA1 + z2 * sA2);
    B += (size_t)(z1 * sB1 + z2 * sB2);
    C += (size_t)(z1 * sC1 + z2 * sC2);

    int tid = threadIdx.x;
    int wid = tid >> 5;
    int wm = wid & 1, wn = wid >> 1;          // 2x2 warps of 64x64
    int bm0 = blockIdx.y * BM, bn0 = blockIdx.x * BN;

    auto load_stage = [&](int kt, int buf) {
        float* As = buf ? As1 : As0;
        float* Bs = buf ? Bs1 : Bs0;
        #pragma unroll
        for (int it = 0; it < 8; it++) {      // A tile: 128 x 32
            int idx = tid + it * 128;
            int r = idx >> 3, c = (idx & 7) << 2;
            cp_async16(&As[r * AKP + c],
                       A + (size_t)(bm0 + r) * lda + kt + c);
        }
        #pragma unroll
        for (int it = 0; it < 8; it++) {      // B tile: 32(k) x 128(n)
            int idx = tid + it * 128;
            int r = idx >> 5, c = (idx & 31) << 2;
            cp_async16(&Bs[r * BNP + c],
                       B + (size_t)(kt + r) * ldb + bn0 + c);
        }
    };

    wmma::fragment<wmma::accumulator, 16, 16, 8, float> acc[4][4];
    #pragma unroll
    for (int i = 0; i < 4; i++)
        #pragma unroll
        for (int j = 0; j < 4; j++) wmma::fill_fragment(acc[i][j], 0.0f);

    int T = K / BK;
    load_stage(0, 0);
    cp_commit();

    for (int t = 0; t < T; t++) {
        if (t + 1 < T) load_stage((t + 1) * BK, (t + 1) & 1);
        cp_commit();
        cp_wait1();
        __syncthreads();
        int buf = t & 1;
        float* As = buf ? As1 : As0;
        float* Bs = buf ? Bs1 : Bs0;
        #pragma unroll
        for (int ks = 0; ks < BK; ks += 8) {
            wmma::fragment<wmma::matrix_a, 16, 16, 8, wmma::precision::tf32, wmma::row_major> af[4];
            #pragma unroll
            for (int i = 0; i < 4; i++)
                wmma::load_matrix_sync(af[i], &As[(wm * 64 + i * 16) * AKP + ks], AKP);
            #pragma unroll
            for (int j = 0; j < 4; j++) {
                wmma::fragment<wmma::matrix_b, 16, 16, 8, wmma::precision::tf32, wmma::row_major> bf;
                wmma::load_matrix_sync(bf, &Bs[ks * BNP + wn * 64 + j * 16], BNP);
                #pragma unroll
                for (int i = 0; i < 4; i++)
                    wmma::mma_sync(acc[i][j], af[i], bf, acc[i][j]);
            }
        }
        __syncthreads();
    }
    #pragma unroll
    for (int i = 0; i < 4; i++)
        #pragma unroll
        for (int j = 0; j < 4; j++) {
            if (RND) {
                #pragma unroll
                for (int e = 0; e < acc[i][j].num_elements; e++)
                    acc[i][j].x[e] = rtf32(acc[i][j].x[e]);
            }
            wmma::store_matrix_sync(C + (size_t)(bm0 + wm * 64 + i * 16) * ldc + bn0 + wn * 64 + j * 16,
                                    acc[i][j], ldc, wmma::mem_row_major);
        }
}

static const int SMEM_G = 2 * (128*36 + 32*132) * 4;    // 70656

// ---------------- tf32 WMMA GEMM, 2-stage BT (attention scores) ---------------
// C[M,N] = A[M,K] * B[N,K]^T; 128x128 tile, 4 warps of 64x64, BK=32.
__global__ void __launch_bounds__(128, 3)
k_gemmBT(const float* __restrict__ A, int lda, long long sA1,
         const float* __restrict__ B, int ldb, long long sB1,
         float*       __restrict__ C, int ldc, long long sC1,
         int K) {
    constexpr int BM = 128, BN = 128, BK = 32;
    constexpr int AKP = BK + 4;    // 36
    constexpr int AS_SZ = BM * AKP;
    constexpr int BS_SZ = BN * AKP;
    extern __shared__ __align__(16) float smem[];
    float* As0 = smem;
    float* As1 = smem + AS_SZ;
    float* Bs0 = smem + 2 * AS_SZ;
    float* Bs1 = smem + 2 * AS_SZ + BS_SZ;

    int z  = blockIdx.z;
    A += (size_t)z * sA1;
    B += (size_t)z * sB1;
    C += (size_t)z * sC1;

    int tid = threadIdx.x;
    int wid = tid >> 5;
    int wm = wid & 1, wn = wid >> 1;
    int bm0 = blockIdx.y * BM, bn0 = blockIdx.x * BN;

    auto load_stage = [&](int kt, int buf) {
        float* As = buf ? As1 : As0;
        float* Bs = buf ? Bs1 : Bs0;
        #pragma unroll
        for (int it = 0; it < 8; it++) {
            int idx = tid + it * 128;
            int r = idx >> 3, c = (idx & 7) << 2;
            cp_async16(&As[r * AKP + c],
                       A + (size_t)(bm0 + r) * lda + kt + c);
        }
        #pragma unroll
        for (int it = 0; it < 8; it++) {
            int idx = tid + it * 128;
            int r = idx >> 3, c = (idx & 7) << 2;
            cp_async16(&Bs[r * AKP + c],
                       B + (size_t)(bn0 + r) * ldb + kt + c);
        }
    };

    wmma::fragment<wmma::accumulator, 16, 16, 8, float> acc[4][4];
    #pragma unroll
    for (int i = 0; i < 4; i++)
        #pragma unroll
        for (int j = 0; j < 4; j++) wmma::fill_fragment(acc[i][j], 0.0f);

    int T = K / BK;
    load_stage(0, 0);
    cp_commit();

    for (int t = 0; t < T; t++) {
        if (t + 1 < T) load_stage((t + 1) * BK, (t + 1) & 1);
        cp_commit();
        cp_wait1();
        __syncthreads();
        int buf = t & 1;
        float* As = buf ? As1 : As0;
        float* Bs = buf ? Bs1 : Bs0;
        #pragma unroll
        for (int ks = 0; ks < BK; ks += 8) {
            wmma::fragment<wmma::matrix_a, 16, 16, 8, wmma::precision::tf32, wmma::row_major> af[4];
            #pragma unroll
            for (int i = 0; i < 4; i++)
                wmma::load_matrix_sync(af[i], &As[(wm * 64 + i * 16) * AKP + ks], AKP);
            #pragma unroll
            for (int j = 0; j < 4; j++) {
                wmma::fragment<wmma::matrix_b, 16, 16, 8, wmma::precision::tf32, wmma::col_major> bf;
                wmma::load_matrix_sync(bf, &Bs[(wn * 64 + j * 16) * AKP + ks], AKP);
                #pragma unroll
                for (int i = 0; i < 4; i++)
                    wmma::mma_sync(acc[i][j], af[i], bf, acc[i][j]);
            }
        }
        __syncthreads();
    }
    #pragma unroll
    for (int i = 0; i < 4; i++)
        #pragma unroll
        for (int j = 0; j < 4; j++)
            wmma::store_matrix_sync(C + (size_t)(bm0 + wm * 64 + i * 16) * ldc + bn0 + wn * 64 + j * 16,
                                    acc[i][j], ldc, wmma::mem_row_major);
}

static const int SMEM_BT = (2*128*36 + 2*128*36) * 4;   // 73728

// ---------------- K4: qkv bias + RMSNorm + RoPE + layout [B,H,S,HD] -----------
__global__ void k_qkvpost(const float* __restrict__ qkv_b,
                          const float* __restrict__ cosb,
                          const float* __restrict__ sinb,
                          const float* __restrict__ nqw,
                          const float* __restrict__ nkw) {
    __shared__ float sh4[4];
    __shared__ float bufq[HD_], bufk[HD_];
    int tok = blockIdx.x, h = blockIdx.y, d = threadIdx.x;
    int b = tok >> 10, s = tok & 1023;
    size_t base = (size_t)tok * D3 + h * HD_;
    float qv = g_qkv[base + d]          + qkv_b[h * HD_ + d];
    float kv = g_qkv[base + D_ + d]     + qkv_b[D_ + h * HD_ + d];
    float vv = g_qkv[base + 2*D_ + d]   + qkv_b[2*D_ + h * HD_ + d];
    float sq = block_sum<4>(qv * qv, sh4);
    float sk = block_sum<4>(kv * kv, sh4);
    float rq = rsqrtf(sq * (1.f / HD_) + 1e-6f);
    float rk = rsqrtf(sk * (1.f / HD_) + 1e-6f);
    float qn = qv * rq * nqw[d];
    float kn = kv * rk * nkw[d];
    bufq[d] = qn; bufk[d] = kn;
    __syncthreads();
    float qo = qn, ko = kn;
    if (d < RD_) {
        int i = d >> 1;
        float c  = cosb[s * (RD_/2) + i];
        float sn = sinb[s * (RD_/2) + i];
        if ((d & 1) == 0) { qo = bufq[d] * c - bufq[d+1] * sn;
                            ko = bufk[d] * c - bufk[d+1] * sn; }
        else              { qo = bufq[d-1] * sn + bufq[d] * c;
                            ko = bufk[d-1] * sn + bufk[d] * c; }
    }
    size_t ob = ((size_t)(b * H_ + h) * S_ + s) * HD_ + d;
    g_q[ob] = rtf32(qo * 0.08838834764831845f);  // 1/sqrt(HD) folded into Q
    g_k[ob] = rtf32(ko);
    g_v[ob] = rtf32(vv);
}

// ---------------- K6: softmax over rows of g_s (warp per row, float4) ---------
__global__ void k_softmax() {
    int r = blockIdx.x * 8 + (threadIdx.x >> 5);
    int lane = threadIdx.x & 31;
    float4* row = reinterpret_cast<float4*>(g_s + (size_t)r * S_);
    float4 x[8];
    float mx = -1e30f;
    #pragma unroll
    for (int i = 0; i < 8; i++) {
        x[i] = row[lane + 32*i];
        mx = fmaxf(mx, fmaxf(fmaxf(x[i].x, x[i].y), fmaxf(x[i].z, x[i].w)));
    }
    #pragma unroll
    for (int o = 16; o > 0; o >>= 1) mx = fmaxf(mx, __shfl_xor_sync(0xffffffffu, mx, o));
    float sm = 0.f;
    #pragma unroll
    for (int i = 0; i < 8; i++) {
        x[i].x = __expf(x[i].x - mx); x[i].y = __expf(x[i].y - mx);
        x[i].z = __expf(x[i].z - mx); x[i].w = __expf(x[i].w - mx);
        sm += x[i].x + x[i].y + x[i].z + x[i].w;
    }
    #pragma unroll
    for (int o = 16; o > 0; o >>= 1) sm += __shfl_xor_sync(0xffffffffu, sm, o);
    float inv = 1.f / sm;
    #pragma unroll
    for (int i = 0; i < 8; i++) {
        x[i].x = rtf32(x[i].x * inv); x[i].y = rtf32(x[i].y * inv);
        x[i].z = rtf32(x[i].z * inv); x[i].w = rtf32(x[i].w * inv);
        row[lane + 32*i] = x[i];
    }
}

// ---------------- K9: bias + gate + residual ----------------------------------
__global__ void k_final(const float* __restrict__ x,
                        const float* __restrict__ out_b,
                        float* __restrict__ out) {
    size_t idx = ((size_t)blockIdx.x * blockDim.x + threadIdx.x) * 4;
    int n = (int)(idx & (D_ - 1));
    int m = (int)(idx >> 11);
    int b = m >> 10;
    const float* gate = g_m3 + b * D3 + 2 * D_;
    float4 t  = *reinterpret_cast<float4*>(&g_t[idx]);
    float4 xr = *reinterpret_cast<const float4*>(&x[idx]);
    float4 o;
    o.x = (t.x + out_b[n+0]) * gate[n+0] + xr.x;
    o.y = (t.y + out_b[n+1]) * gate[n+1] + xr.y;
    o.z = (t.z + out_b[n+2]) * gate[n+2] + xr.z;
    o.w = (t.w + out_b[n+3]) * gate[n+3] + xr.w;
    *reinterpret_cast<float4*>(&out[idx]) = o;
}

// ---------------- launch ------------------------------------------------------
extern "C" void kernel_launch(void* const* d_in, const int* in_sizes, int n_in,
                              void* d_out, int out_size) {
    const float* x     = (const float*)d_in[0];
    const float* mod   = (const float*)d_in[1];
    const float* cosb  = (const float*)d_in[2];
    const float* sinb  = (const float*)d_in[3];
    const float* qkv_w = (const float*)d_in[4];
    const float* qkv_b = (const float*)d_in[5];
    const float* mod_w = (const float*)d_in[6];
    const float* mod_b = (const float*)d_in[7];
    const float* out_w = (const float*)d_in[8];
    const float* out_b = (const float*)d_in[9];
    const float* nqw   = (const float*)d_in[10];
    const float* nkw   = (const float*)d_in[11];
    float* out = (float*)d_out;

    float *p_xn, *p_qkv, *p_q, *p_k, *p_v, *p_s, *p_o, *p_t, *p_qkvw, *p_outw;
    cudaGetSymbolAddress((void**)&p_xn, g_xn);
    cudaGetSymbolAddress((void**)&p_qkv, g_qkv);
    cudaGetSymbolAddress((void**)&p_q, g_q);
    cudaGetSymbolAddress((void**)&p_k, g_k);
    cudaGetSymbolAddress((void**)&p_v, g_v);
    cudaGetSymbolAddress((void**)&p_s, g_s);
    cudaGetSymbolAddress((void**)&p_o, g_o);
    cudaGetSymbolAddress((void**)&p_t, g_t);
    cudaGetSymbolAddress((void**)&p_qkvw, g_qkvw);
    cudaGetSymbolAddress((void**)&p_outw, g_outw);

    cudaFuncSetAttribute(k_gemm<false>, cudaFuncAttributeMaxDynamicSharedMemorySize, SMEM_G);
    cudaFuncSetAttribute(k_gemm<true>,  cudaFuncAttributeMaxDynamicSharedMemorySize, SMEM_G);
    cudaFuncSetAttribute(k_gemmBT, cudaFuncAttributeMaxDynamicSharedMemorySize, SMEM_BT);

    // 0) tf32-round the big weights into scratch
    k_round<<<(D_*D3)/(4*256), 256>>>(qkv_w, p_qkvw);
    k_round<<<(D_*D_)/(4*256), 256>>>(out_w, p_outw);
    // 1) m3 = mod @ mod_w + mod_b
    k_mod_part<<<dim3(D3/128, KC), 128>>>(mod, mod_w);
    k_mod_red<<<(B_*D3)/256, 256>>>(mod_b);
    // 2) xn = modulate(layernorm(x)) [tf32-rounded]
    k_lnmod<<<NT, 256>>>(x);
    // 3) qkv = xn @ qkv_w  (bias folded into K4)
    k_gemm<false><<<dim3(D3/128, NT/128), 128, SMEM_G>>>(
        p_xn, D_, 0, 0, p_qkvw, D3, 0, 0, p_qkv, D3, 0, 0, D_, 1);
    // 4) bias + rmsnorm + rope -> q,k,v [B,H,S,HD]  [tf32-rounded]
    k_qkvpost<<<dim3(NT, H_), HD_>>>(qkv_b, cosb, sinb, nqw, nkw);
    // 5) scores = Q @ K^T (per b,h); Q already carries 1/sqrt(HD)
    k_gemmBT<<<dim3(S_/128, S_/128, B_*H_), 128, SMEM_BT>>>(
        p_q, HD_, (long long)S_*HD_,
        p_k, HD_, (long long)S_*HD_,
        p_s, S_,  (long long)S_*S_, HD_);
    // 6) softmax rows [tf32-rounded]
    k_softmax<<<(B_*H_*S_)/8, 256>>>();
    // 7) O = P @ V  -> [B,S,H,HD] (strided C) [accum rounded for next GEMM]
    k_gemm<true><<<dim3(1, S_/128, B_*H_), 128, SMEM_G>>>(
        p_s, S_,  (long long)H_*S_*S_,  (long long)S_*S_,
        p_v, HD_, (long long)H_*S_*HD_, (long long)S_*HD_,
        p_o, D_,  (long long)S_*D_,     (long long)HD_, S_, H_);
    // 8) t = O @ out_w
    k_gemm<false><<<dim3(D_/128, NT/128), 128, SMEM_G>>>(
        p_o, D_, 0, 0, p_outw, D_, 0, 0, p_t, D_, 0, 0, D_, 1);
    // 9) out = (t + out_b) * gate + x
    k_final<<<(NT*D_)/(4*256), 256>>>(x, out_b, out);
}

// round 11
// speedup vs baseline: 1.2135x; 1.2135x over previous
#include <cuda_runtime.h>
#include <mma.h>
#include <cstdint>

using namespace nvcuda;

// Shapes
#define B_  4
#define S_  1024
#define D_  2048
#define H_  16
#define HD_ 128
#define RD_ 64
#define NT  (B_*S_)      // 4096 tokens
#define D3  (3*D_)       // 6144
#define KC  8            // mod-gemm split-K chunks

// ---------------- scratch (static device arrays; allocation-free) -------------
__device__ float g_m3p[KC*B_*D3];
__device__ float g_m3[B_*D3];
__device__ float g_xn[NT*D_];
__device__ float g_qkv[(size_t)NT*D3];
__device__ float g_q[(size_t)B_*H_*S_*HD_];
__device__ float g_k[(size_t)B_*H_*S_*HD_];
__device__ float g_v[(size_t)B_*H_*S_*HD_];
__device__ float g_s[(size_t)B_*H_*S_*S_];   // 256 MB scores (exp'd)
__device__ float g_l[(size_t)B_*H_*S_];      // row sums of exp
__device__ float g_o[(size_t)NT*D_];
__device__ float g_t[(size_t)NT*D_];
__device__ float g_qkvw[(size_t)D_*D3];      // tf32-rounded qkv_w
__device__ float g_outw[(size_t)D_*D_];      // tf32-rounded out_w

// ---------------- tf32 round-to-nearest helper --------------------------------
__device__ __forceinline__ float rtf32(float x) {
    float r;
    asm("cvt.rna.tf32.f32 %0, %1;" : "=f"(r) : "f"(x));
    return r;
}

// ---------------- cp.async helpers -------------------------------------------
__device__ __forceinline__ void cp_async16(void* smem_dst, const void* gmem_src) {
    uint32_t s = (uint32_t)__cvta_generic_to_shared(smem_dst);
    asm volatile("cp.async.cg.shared.global [%0], [%1], 16;\n" :: "r"(s), "l"(gmem_src));
}
__device__ __forceinline__ void cp_commit() {
    asm volatile("cp.async.commit_group;\n" ::: "memory");
}
__device__ __forceinline__ void cp_wait1() {
    asm volatile("cp.async.wait_group 1;\n" ::: "memory");
}

// ---------------- helpers ----------------------------------------------------
template<int NW>
__device__ __forceinline__ float block_sum(float v, float* sh) {
    #pragma unroll
    for (int o = 16; o > 0; o >>= 1) v += __shfl_xor_sync(0xffffffffu, v, o);
    int w = threadIdx.x >> 5;
    if ((threadIdx.x & 31) == 0) sh[w] = v;
    __syncthreads();
    float r = 0.f;
    #pragma unroll
    for (int i = 0; i < NW; i++) r += sh[i];
    __syncthreads();
    return r;
}

// ---------------- K0: tf32-round weights to scratch ---------------------------
__global__ void k_round(const float* __restrict__ in, float* __restrict__ o) {
    int i = blockIdx.x * 256 + threadIdx.x;
    float4 v = reinterpret_cast<const float4*>(in)[i];
    v.x = rtf32(v.x); v.y = rtf32(v.y); v.z = rtf32(v.z); v.w = rtf32(v.w);
    reinterpret_cast<float4*>(o)[i] = v;
}

// ---------------- K1: mod GEMM (split-K partials, deterministic) --------------
__global__ void k_mod_part(const float* __restrict__ mod,
                           const float* __restrict__ mod_w) {
    __shared__ float sm[B_*256];
    int kc = blockIdx.y;
    int k0 = kc * 256;
    for (int i = threadIdx.x; i < B_*256; i += blockDim.x)
        sm[i] = mod[(i >> 8) * D_ + k0 + (i & 255)];
    __syncthreads();
    int j = blockIdx.x * 128 + threadIdx.x;
    float a0=0.f, a1=0.f, a2=0.f, a3=0.f;
    #pragma unroll 4
    for (int k = 0; k < 256; k++) {
        float w = mod_w[(size_t)(k0 + k) * D3 + j];
        a0 = fmaf(sm[k],       w, a0);
        a1 = fmaf(sm[256 + k], w, a1);
        a2 = fmaf(sm[512 + k], w, a2);
        a3 = fmaf(sm[768 + k], w, a3);
    }
    float* p = g_m3p + (size_t)kc * (B_*D3);
    p[0*D3 + j] = a0; p[1*D3 + j] = a1; p[2*D3 + j] = a2; p[3*D3 + j] = a3;
}

__global__ void k_mod_red(const float* __restrict__ mod_b) {
    int i = blockIdx.x * 256 + threadIdx.x;   // 0 .. B_*D3-1
    float s = 0.f;
    #pragma unroll
    for (int c = 0; c < KC; c++) s += g_m3p[c * (B_*D3) + i];
    g_m3[i] = s + mod_b[i % D3];
}

// ---------------- K2: LayerNorm + AdaLN modulation (tf32-rounded out) ---------
__global__ void k_lnmod(const float* __restrict__ x) {
    __shared__ float sh[8];
    int m = blockIdx.x;       // token
    int b = m >> 10;
    int t = threadIdx.x;
    const float* xr = x + (size_t)m * D_;
    float4 v0 = *reinterpret_cast<const float4*>(xr + t*4);
    float4 v1 = *reinterpret_cast<const float4*>(xr + 1024 + t*4);
    float s = v0.x+v0.y+v0.z+v0.w + v1.x+v1.y+v1.z+v1.w;
    s = block_sum<8>(s, sh);
    float mean = s * (1.f / D_);
    float d0=v0.x-mean, d1=v0.y-mean, d2=v0.z-mean, d3=v0.w-mean;
    float d4=v1.x-mean, d5=v1.y-mean, d6=v1.z-mean, d7=v1.w-mean;
    float ss = d0*d0+d1*d1+d2*d2+d3*d3+d4*d4+d5*d5+d6*d6+d7*d7;
    ss = block_sum<8>(ss, sh);
    float rinv = rsqrtf(ss * (1.f / D_) + 1e-6f);
    const float* mb  = g_m3 + b * D3;        // bias
    const float* msc = mb + D_;              // scale
    int e0 = t*4, e1 = 1024 + t*4;
    float4 o0, o1;
    o0.x = rtf32(d0*rinv*(1.f+msc[e0+0]) + mb[e0+0]);
    o0.y = rtf32(d1*rinv*(1.f+msc[e0+1]) + mb[e0+1]);
    o0.z = rtf32(d2*rinv*(1.f+msc[e0+2]) + mb[e0+2]);
    o0.w = rtf32(d3*rinv*(1.f+msc[e0+3]) + mb[e0+3]);
    o1.x = rtf32(d4*rinv*(1.f+msc[e1+0]) + mb[e1+0]);
    o1.y = rtf32(d5*rinv*(1.f+msc[e1+1]) + mb[e1+1]);
    o1.z = rtf32(d6*rinv*(1.f+msc[e1+2]) + mb[e1+2]);
    o1.w = rtf32(d7*rinv*(1.f+msc[e1+3]) + mb[e1+3]);
    float* xo = g_xn + (size_t)m * D_;
    *reinterpret_cast<float4*>(xo + e0) = o0;
    *reinterpret_cast<float4*>(xo + e1) = o1;
}

// ---------------- tf32 WMMA GEMM, 2-stage BT (scores, optional exp epi) -------
// C[M,N] = A[M,K] * B[N,K]^T; 128x128 tile, 4 warps of 64x64, BK=32.
template<bool EXPE>
__global__ void __launch_bounds__(128, 2)
k_gemmBT(const float* __restrict__ A, int lda, long long sA1,
         const float* __restrict__ B, int ldb, long long sB1,
         float*       __restrict__ C, int ldc, long long sC1,
         int K) {
    constexpr int BM = 128, BN = 128, BK = 32;
    constexpr int AKP = BK + 8;
    constexpr int AS_SZ = BM * AKP;
    constexpr int BS_SZ = BN * AKP;
    extern __shared__ __align__(16) float smem[];
    float* As0 = smem;
    float* As1 = smem + AS_SZ;
    float* Bs0 = smem + 2 * AS_SZ;
    float* Bs1 = smem + 2 * AS_SZ + BS_SZ;

    int z  = blockIdx.z;
    A += (size_t)z * sA1;
    B += (size_t)z * sB1;
    C += (size_t)z * sC1;

    int tid = threadIdx.x;
    int wid = tid >> 5;
    int wm = wid & 1, wn = wid >> 1;
    int bm0 = blockIdx.y * BM, bn0 = blockIdx.x * BN;

    auto load_stage = [&](int kt, int buf) {
        float* As = buf ? As1 : As0;
        float* Bs = buf ? Bs1 : Bs0;
        #pragma unroll
        for (int it = 0; it < 8; it++) {
            int idx = tid + it * 128;
            int r = idx >> 3, c = (idx & 7) << 2;
            cp_async16(&As[r * AKP + c],
                       A + (size_t)(bm0 + r) * lda + kt + c);
        }
        #pragma unroll
        for (int it = 0; it < 8; it++) {
            int idx = tid + it * 128;
            int r = idx >> 3, c = (idx & 7) << 2;
            cp_async16(&Bs[r * AKP + c],
                       B + (size_t)(bn0 + r) * ldb + kt + c);
        }
    };

    wmma::fragment<wmma::accumulator, 16, 16, 8, float> acc[4][4];
    #pragma unroll
    for (int i = 0; i < 4; i++)
        #pragma unroll
        for (int j = 0; j < 4; j++) wmma::fill_fragment(acc[i][j], 0.0f);

    int T = K / BK;
    load_stage(0, 0);
    cp_commit();

    for (int t = 0; t < T; t++) {
        if (t + 1 < T) load_stage((t + 1) * BK, (t + 1) & 1);
        cp_commit();
        cp_wait1();
        __syncthreads();
        int buf = t & 1;
        float* As = buf ? As1 : As0;
        float* Bs = buf ? Bs1 : Bs0;
        #pragma unroll
        for (int ks = 0; ks < BK; ks += 8) {
            wmma::fragment<wmma::matrix_a, 16, 16, 8, wmma::precision::tf32, wmma::row_major> af[4];
            #pragma unroll
            for (int i = 0; i < 4; i++)
                wmma::load_matrix_sync(af[i], &As[(wm * 64 + i * 16) * AKP + ks], AKP);
            #pragma unroll
            for (int j = 0; j < 4; j++) {
                wmma::fragment<wmma::matrix_b, 16, 16, 8, wmma::precision::tf32, wmma::col_major> bf;
                wmma::load_matrix_sync(bf, &Bs[(wn * 64 + j * 16) * AKP + ks], AKP);
                #pragma unroll
                for (int i = 0; i < 4; i++)
                    wmma::mma_sync(acc[i][j], af[i], bf, acc[i][j]);
            }
        }
        __syncthreads();
    }
    #pragma unroll
    for (int i = 0; i < 4; i++)
        #pragma unroll
        for (int j = 0; j < 4; j++) {
            if (EXPE) {
                #pragma unroll
                for (int e = 0; e < acc[i][j].num_elements; e++)
                    acc[i][j].x[e] = rtf32(__expf(acc[i][j].x[e]));
            }
            wmma::store_matrix_sync(C + (size_t)(bm0 + wm * 64 + i * 16) * ldc + bn0 + wn * 64 + j * 16,
                                    acc[i][j], ldc, wmma::mem_row_major);
        }
}

static const int SMEM_BT = (2*128*40 + 2*128*40) * 4;   // 81920

// ---------------- tf32 WMMA GEMM, 3-stage, ONE sync per tile ------------------
// C[M,N] = A[M,K] * B[K,N]; 128x128 tile, 4 warps of 64x64, BK=32.
// SUMR: also emit per-row sums of A (full-K per CTA required) into Lv.
template<bool RND, bool SUMR>
__global__ void __launch_bounds__(128, 2)
k_gemm3(const float* __restrict__ A, int lda, long long sA1, long long sA2,
        const float* __restrict__ B, int ldb, long long sB1, long long sB2,
        float*       __restrict__ C, int ldc, long long sC1, long long sC2,
        int K, int zdiv, float* __restrict__ Lv) {
    constexpr int BM = 128, BN = 128, BK = 32;
    constexpr int AKP = BK + 8;    // 40
    constexpr int BNP = BN + 8;    // 136
    constexpr int AS_SZ = BM * AKP;    // 5120
    constexpr int BS_SZ = BK * BNP;    // 4352
    constexpr int STG = AS_SZ + BS_SZ; // 9472 floats per stage
    extern __shared__ __align__(16) float smem[];

    int z  = blockIdx.z;
    int z1 = z / zdiv, z2 = z - z1 * zdiv;
    A += (size_t)(z1 * sA1 + z2 * sA2);
    B += (size_t)(z1 * sB1 + z2 * sB2);
    C += (size_t)(z1 * sC1 + z2 * sC2);

    int tid = threadIdx.x;
    int wid = tid >> 5;
    int wm = wid & 1, wn = wid >> 1;          // 2x2 warps of 64x64
    int bm0 = blockIdx.y * BM, bn0 = blockIdx.x * BN;

    auto load_stage = [&](int kt, int s) {
        float* As = smem + s * STG;
        float* Bs = As + AS_SZ;
        #pragma unroll
        for (int it = 0; it < 8; it++) {      // A tile: 128 x 32
            int idx = tid + it * 128;
            int r = idx >> 3, c = (idx & 7) << 2;
            cp_async16(&As[r * AKP + c],
                       A + (size_t)(bm0 + r) * lda + kt + c);
        }
        #pragma unroll
        for (int it = 0; it < 8; it++) {      // B tile: 32(k) x 128(n)
            int idx = tid + it * 128;
            int r = idx >> 5, c = (idx & 31) << 2;
            cp_async16(&Bs[r * BNP + c],
                       B + (size_t)(kt + r) * ldb + bn0 + c);
        }
    };

    wmma::fragment<wmma::accumulator, 16, 16, 8, float> acc[4][4];
    #pragma unroll
    for (int i = 0; i < 4; i++)
        #pragma unroll
        for (int j = 0; j < 4; j++) wmma::fill_fragment(acc[i][j], 0.0f);

    float lsum = 0.f;
    int T = K / BK;
    load_stage(0, 0);  cp_commit();
    load_stage(BK, 1); cp_commit();

    int sbuf = 0;       // stage of tile t (t % 3)
    for (int t = 0; t < T; t++) {
        cp_wait1();                     // tile t landed
        __syncthreads();                // visibility + everyone done with t-1
        int nt = t + 2;
        if (nt < T) {
            int ns = sbuf + 2; if (ns >= 3) ns -= 3;
            load_stage(nt * BK, ns);
            cp_commit();
        }
        float* As = smem + sbuf * STG;
        float* Bs = As + AS_SZ;
        if (SUMR) {                     // thread r sums row r (rotated, no conflicts)
            const float* ar = &As[tid * AKP];
            #pragma unroll
            for (int c = 0; c < BK; c++) lsum += ar[(tid + c) & 31];
        }
        #pragma unroll
        for (int ks = 0; ks < BK; ks += 8) {
            wmma::fragment<wmma::matrix_a, 16, 16, 8, wmma::precision::tf32, wmma::row_major> af[4];
            #pragma unroll
            for (int i = 0; i < 4; i++)
                wmma::load_matrix_sync(af[i], &As[(wm * 64 + i * 16) * AKP + ks], AKP);
            #pragma unroll
            for (int j = 0; j < 4; j++) {
                wmma::fragment<wmma::matrix_b, 16, 16, 8, wmma::precision::tf32, wmma::row_major> bf;
                wmma::load_matrix_sync(bf, &Bs[ks * BNP + wn * 64 + j * 16], BNP);
                #pragma unroll
                for (int i = 0; i < 4; i++)
                    wmma::mma_sync(acc[i][j], af[i], bf, acc[i][j]);
            }
        }
        if (++sbuf == 3) sbuf = 0;
    }
    if (SUMR)
        Lv[(size_t)z * S_ + bm0 + tid] = lsum;
    #pragma unroll
    for (int i = 0; i < 4; i++)
        #pragma unroll
        for (int j = 0; j < 4; j++) {
            if (RND) {
                #pragma unroll
                for (int e = 0; e < acc[i][j].num_elements; e++)
                    acc[i][j].x[e] = rtf32(acc[i][j].x[e]);
            }
            wmma::store_matrix_sync(C + (size_t)(bm0 + wm * 64 + i * 16) * ldc + bn0 + wn * 64 + j * 16,
                                    acc[i][j], ldc, wmma::mem_row_major);
        }
}

static const int SMEM_G3 = 3 * (128*40 + 32*136) * 4;   // 113664

// ---------------- K4: qkv bias + RMSNorm + RoPE + layout [B,H,S,HD] -----------
__global__ void k_qkvpost(const float* __restrict__ qkv_b,
                          const float* __restrict__ cosb,
                          const float* __restrict__ sinb,
                          const float* __restrict__ nqw,
                          const float* __restrict__ nkw) {
    __shared__ float sh4[4];
    __shared__ float bufq[HD_], bufk[HD_];
    int tok = blockIdx.x, h = blockIdx.y, d = threadIdx.x;
    int b = tok >> 10, s = tok & 1023;
    size_t base = (size_t)tok * D3 + h * HD_;
    float qv = g_qkv[base + d]          + qkv_b[h * HD_ + d];
    float kv = g_qkv[base + D_ + d]     + qkv_b[D_ + h * HD_ + d];
    float vv = g_qkv[base + 2*D_ + d]   + qkv_b[2*D_ + h * HD_ + d];
    float sq = block_sum<4>(qv * qv, sh4);
    float sk = block_sum<4>(kv * kv, sh4);
    float rq = rsqrtf(sq * (1.f / HD_) + 1e-6f);
    float rk = rsqrtf(sk * (1.f / HD_) + 1e-6f);
    float qn = qv * rq * nqw[d];
    float kn = kv * rk * nkw[d];
    bufq[d] = qn; bufk[d] = kn;
    __syncthreads();
    float qo = qn, ko = kn;
    if (d < RD_) {
        int i = d >> 1;
        float c  = cosb[s * (RD_/2) + i];
        float sn = sinb[s * (RD_/2) + i];
        if ((d & 1) == 0) { qo = bufq[d] * c - bufq[d+1] * sn;
                            ko = bufk[d] * c - bufk[d+1] * sn; }
        else              { qo = bufq[d-1] * sn + bufq[d] * c;
                            ko = bufk[d-1] * sn + bufk[d] * c; }
    }
    size_t ob = ((size_t)(b * H_ + h) * S_ + s) * HD_ + d;
    g_q[ob] = rtf32(qo * 0.08838834764831845f);  // 1/sqrt(HD) folded into Q
    g_k[ob] = rtf32(ko);
    g_v[ob] = rtf32(vv);
}

// ---------------- K7: normalize O by row sums, tf32-round ---------------------
__global__ void k_onorm() {
    size_t idx = ((size_t)blockIdx.x * blockDim.x + threadIdx.x) * 4;
    int n = (int)(idx & (D_ - 1));
    int m = (int)(idx >> 11);        // token
    int b = m >> 10, s = m & 1023;
    int h = n >> 7;
    float inv = 1.f / g_l[((size_t)(b * H_ + h)) * S_ + s];
    float4 v = *reinterpret_cast<float4*>(&g_o[idx]);
    v.x = rtf32(v.x * inv); v.y = rtf32(v.y * inv);
    v.z = rtf32(v.z * inv); v.w = rtf32(v.w * inv);
    *reinterpret_cast<float4*>(&g_o[idx]) = v;
}

// ---------------- K9: bias + gate + residual ----------------------------------
__global__ void k_final(const float* __restrict__ x,
                        const float* __restrict__ out_b,
                        float* __restrict__ out) {
    size_t idx = ((size_t)blockIdx.x * blockDim.x + threadIdx.x) * 4;
    int n = (int)(idx & (D_ - 1));
    int m = (int)(idx >> 11);
    int b = m >> 10;
    const float* gate = g_m3 + b * D3 + 2 * D_;
    float4 t  = *reinterpret_cast<float4*>(&g_t[idx]);
    float4 xr = *reinterpret_cast<const float4*>(&x[idx]);
    float4 o;
    o.x = (t.x + out_b[n+0]) * gate[n+0] + xr.x;
    o.y = (t.y + out_b[n+1]) * gate[n+1] + xr.y;
    o.z = (t.z + out_b[n+2]) * gate[n+2] + xr.z;
    o.w = (t.w + out_b[n+3]) * gate[n+3] + xr.w;
    *reinterpret_cast<float4*>(&out[idx]) = o;
}

// ---------------- launch ------------------------------------------------------
extern "C" void kernel_launch(void* const* d_in, const int* in_sizes, int n_in,
                              void* d_out, int out_size) {
    const float* x     = (const float*)d_in[0];
    const float* mod   = (const float*)d_in[1];
    const float* cosb  = (const float*)d_in[2];
    const float* sinb  = (const float*)d_in[3];
    const float* qkv_w = (const float*)d_in[4];
    const float* qkv_b = (const float*)d_in[5];
    const float* mod_w = (const float*)d_in[6];
    const float* mod_b = (const float*)d_in[7];
    const float* out_w = (const float*)d_in[8];
    const float* out_b = (const float*)d_in[9];
    const float* nqw   = (const float*)d_in[10];
    const float* nkw   = (const float*)d_in[11];
    float* out = (float*)d_out;

    float *p_xn, *p_qkv, *p_q, *p_k, *p_v, *p_s, *p_l, *p_o, *p_t, *p_qkvw, *p_outw;
    cudaGetSymbolAddress((void**)&p_xn, g_xn);
    cudaGetSymbolAddress((void**)&p_qkv, g_qkv);
    cudaGetSymbolAddress((void**)&p_q, g_q);
    cudaGetSymbolAddress((void**)&p_k, g_k);
    cudaGetSymbolAddress((void**)&p_v, g_v);
    cudaGetSymbolAddress((void**)&p_s, g_s);
    cudaGetSymbolAddress((void**)&p_l, g_l);
    cudaGetSymbolAddress((void**)&p_o, g_o);
    cudaGetSymbolAddress((void**)&p_t, g_t);
    cudaGetSymbolAddress((void**)&p_qkvw, g_qkvw);
    cudaGetSymbolAddress((void**)&p_outw, g_outw);

    cudaFuncSetAttribute(k_gemm3<false,false>, cudaFuncAttributeMaxDynamicSharedMemorySize, SMEM_G3);
    cudaFuncSetAttribute(k_gemm3<false,true>,  cudaFuncAttributeMaxDynamicSharedMemorySize, SMEM_G3);
    cudaFuncSetAttribute(k_gemmBT<true>, cudaFuncAttributeMaxDynamicSharedMemorySize, SMEM_BT);

    // 0) tf32-round the big weights into scratch
    k_round<<<(D_*D3)/(4*256), 256>>>(qkv_w, p_qkvw);
    k_round<<<(D_*D_)/(4*256), 256>>>(out_w, p_outw);
    // 1) m3 = mod @ mod_w + mod_b
    k_mod_part<<<dim3(D3/128, KC), 128>>>(mod, mod_w);
    k_mod_red<<<(B_*D3)/256, 256>>>(mod_b);
    // 2) xn = modulate(layernorm(x)) [tf32-rounded]
    k_lnmod<<<NT, 256>>>(x);
    // 3) qkv = xn @ qkv_w  (3-stage GEMM; bias folded into K4)
    k_gemm3<false,false><<<dim3(D3/128, NT/128), 128, SMEM_G3>>>(
        p_xn, D_, 0, 0, p_qkvw, D3, 0, 0, p_qkv, D3, 0, 0, D_, 1, nullptr);
    // 4) bias + rmsnorm + rope -> q,k,v [B,H,S,HD]  [tf32-rounded]
    k_qkvpost<<<dim3(NT, H_), HD_>>>(qkv_b, cosb, sinb, nqw, nkw);
    // 5) E = exp(Q @ K^T) (per b,h); scores bounded (|s|<=11.32), no max needed
    k_gemmBT<true><<<dim3(S_/128, S_/128, B_*H_), 128, SMEM_BT>>>(
        p_q, HD_, (long long)S_*HD_,
        p_k, HD_, (long long)S_*HD_,
        p_s, S_,  (long long)S_*S_, HD_);
    // 6) O' = E @ V  -> [B,S,H,HD] (strided C); also l[row] = sum E (full K per CTA)
    k_gemm3<false,true><<<dim3(1, S_/128, B_*H_), 128, SMEM_G3>>>(
        p_s, S_,  (long long)H_*S_*S_,  (long long)S_*S_,
        p_v, HD_, (long long)H_*S_*HD_, (long long)S_*HD_,
        p_o, D_,  (long long)S_*D_,     (long long)HD_, S_, H_, p_l);
    // 7) O = rtf32(O'/l)
    k_onorm<<<(NT*D_)/(4*256), 256>>>();
    // 8) t = O @ out_w  (3-stage GEMM)
    k_gemm3<false,false><<<dim3(D_/128, NT/128), 128, SMEM_G3>>>(
        p_o, D_, 0, 0, p_outw, D_, 0, 0, p_t, D_, 0, 0, D_, 1, nullptr);
    // 9) out = (t + out_b) * gate + x
    k_final<<<(NT*D_)/(4*256), 256>>>(x, out_b, out);
}

// round 12
// speedup vs baseline: 3.7272x; 3.0714x over previous
#include <cuda_runtime.h>
#include <cuda_fp16.h>
#include <mma.h>
#include <cstdint>

using namespace nvcuda;

// Shapes
#define B_  4
#define S_  1024
#define D_  2048
#define H_  16
#define HD_ 128
#define RD_ 64
#define NT  (B_*S_)      // 4096 tokens
#define D3  (3*D_)       // 6144
#define KC  8            // mod-gemm split-K chunks

// ---------------- scratch (static device arrays; allocation-free) -------------
__device__ float  g_m3p[KC*B_*D3];
__device__ float  g_m3[B_*D3];
__device__ __half g_xnh[(size_t)NT*D_];
__device__ float  g_qkv[(size_t)NT*D3];
__device__ __half g_qh[(size_t)B_*H_*S_*HD_];
__device__ __half g_kh[(size_t)B_*H_*S_*HD_];
__device__ __half g_vh[(size_t)B_*H_*S_*HD_];
__device__ __half g_sh[(size_t)B_*H_*S_*S_];   // 128 MB exp(scores-2)
__device__ float  g_l[(size_t)B_*H_*S_];       // row sums of E
__device__ __half g_oh[(size_t)NT*D_];
__device__ float  g_t[(size_t)NT*D_];          // O' (PV out), then out-proj out
__device__ __half g_qkvwh[(size_t)D_*D3];      // fp16 qkv_w
__device__ __half g_outwh[(size_t)D_*D_];      // fp16 out_w

// ---------------- cp.async helpers -------------------------------------------
__device__ __forceinline__ void cp_async16(void* smem_dst, const void* gmem_src) {
    uint32_t s = (uint32_t)__cvta_generic_to_shared(smem_dst);
    asm volatile("cp.async.cg.shared.global [%0], [%1], 16;\n" :: "r"(s), "l"(gmem_src));
}
__device__ __forceinline__ void cp_commit() {
    asm volatile("cp.async.commit_group;\n" ::: "memory");
}
__device__ __forceinline__ void cp_wait1() {
    asm volatile("cp.async.wait_group 1;\n" ::: "memory");
}

// ---------------- helpers ----------------------------------------------------
template<int NW>
__device__ __forceinline__ float block_sum(float v, float* sh) {
    #pragma unroll
    for (int o = 16; o > 0; o >>= 1) v += __shfl_xor_sync(0xffffffffu, v, o);
    int w = threadIdx.x >> 5;
    if ((threadIdx.x & 31) == 0) sh[w] = v;
    __syncthreads();
    float r = 0.f;
    #pragma unroll
    for (int i = 0; i < NW; i++) r += sh[i];
    __syncthreads();
    return r;
}

// ---------------- K0: round weights to fp16 scratch ---------------------------
__global__ void k_round_h(const float* __restrict__ in, __half* __restrict__ o) {
    int i = blockIdx.x * 256 + threadIdx.x;
    float4 v = reinterpret_cast<const float4*>(in)[i];
    __half2* o2 = reinterpret_cast<__half2*>(o);
    o2[2*i]   = __floats2half2_rn(v.x, v.y);
    o2[2*i+1] = __floats2half2_rn(v.z, v.w);
}

// ---------------- K1: mod GEMM (split-K partials, deterministic) --------------
__global__ void k_mod_part(const float* __restrict__ mod,
                           const float* __restrict__ mod_w) {
    __shared__ float sm[B_*256];
    int kc = blockIdx.y;
    int k0 = kc * 256;
    for (int i = threadIdx.x; i < B_*256; i += blockDim.x)
        sm[i] = mod[(i >> 8) * D_ + k0 + (i & 255)];
    __syncthreads();
    int j = blockIdx.x * 128 + threadIdx.x;
    float a0=0.f, a1=0.f, a2=0.f, a3=0.f;
    #pragma unroll 4
    for (int k = 0; k < 256; k++) {
        float w = mod_w[(size_t)(k0 + k) * D3 + j];
        a0 = fmaf(sm[k],       w, a0);
        a1 = fmaf(sm[256 + k], w, a1);
        a2 = fmaf(sm[512 + k], w, a2);
        a3 = fmaf(sm[768 + k], w, a3);
    }
    float* p = g_m3p + (size_t)kc * (B_*D3);
    p[0*D3 + j] = a0; p[1*D3 + j] = a1; p[2*D3 + j] = a2; p[3*D3 + j] = a3;
}

__global__ void k_mod_red(const float* __restrict__ mod_b) {
    int i = blockIdx.x * 256 + threadIdx.x;
    float s = 0.f;
    #pragma unroll
    for (int c = 0; c < KC; c++) s += g_m3p[c * (B_*D3) + i];
    g_m3[i] = s + mod_b[i % D3];
}

// ---------------- K2: LayerNorm + AdaLN modulation (fp16 out) -----------------
__global__ void k_lnmod(const float* __restrict__ x) {
    __shared__ float sh[8];
    int m = blockIdx.x;       // token
    int b = m >> 10;
    int t = threadIdx.x;
    const float* xr = x + (size_t)m * D_;
    float4 v0 = *reinterpret_cast<const float4*>(xr + t*4);
    float4 v1 = *reinterpret_cast<const float4*>(xr + 1024 + t*4);
    float s = v0.x+v0.y+v0.z+v0.w + v1.x+v1.y+v1.z+v1.w;
    s = block_sum<8>(s, sh);
    float mean = s * (1.f / D_);
    float d0=v0.x-mean, d1=v0.y-mean, d2=v0.z-mean, d3=v0.w-mean;
    float d4=v1.x-mean, d5=v1.y-mean, d6=v1.z-mean, d7=v1.w-mean;
    float ss = d0*d0+d1*d1+d2*d2+d3*d3+d4*d4+d5*d5+d6*d6+d7*d7;
    ss = block_sum<8>(ss, sh);
    float rinv = rsqrtf(ss * (1.f / D_) + 1e-6f);
    const float* mb  = g_m3 + b * D3;        // bias
    const float* msc = mb + D_;              // scale
    int e0 = t*4, e1 = 1024 + t*4;
    float o0 = d0*rinv*(1.f+msc[e0+0]) + mb[e0+0];
    float o1 = d1*rinv*(1.f+msc[e0+1]) + mb[e0+1];
    float o2 = d2*rinv*(1.f+msc[e0+2]) + mb[e0+2];
    float o3 = d3*rinv*(1.f+msc[e0+3]) + mb[e0+3];
    float o4 = d4*rinv*(1.f+msc[e1+0]) + mb[e1+0];
    float o5 = d5*rinv*(1.f+msc[e1+1]) + mb[e1+1];
    float o6 = d6*rinv*(1.f+msc[e1+2]) + mb[e1+2];
    float o7 = d7*rinv*(1.f+msc[e1+3]) + mb[e1+3];
    __half* xo = g_xnh + (size_t)m * D_;
    *reinterpret_cast<__half2*>(xo + e0)     = __floats2half2_rn(o0, o1);
    *reinterpret_cast<__half2*>(xo + e0 + 2) = __floats2half2_rn(o2, o3);
    *reinterpret_cast<__half2*>(xo + e1)     = __floats2half2_rn(o4, o5);
    *reinterpret_cast<__half2*>(xo + e1 + 2) = __floats2half2_rn(o6, o7);
}

// ---------------- fp16 WMMA GEMM, 3-stage, ONE sync per tile ------------------
// C[M,N](f32) = A[M,K](h) * B[K,N](h); 128x128 tile, 4 warps of 64x64, BK=32.
// SUMR: also emit per-row sums of A (full-K per CTA required) into Lv.
template<bool SUMR>
__global__ void __launch_bounds__(128, 2)
k_gemm3h(const __half* __restrict__ A, int lda, long long sA1, long long sA2,
         const __half* __restrict__ B, int ldb, long long sB1, long long sB2,
         float*        __restrict__ C, int ldc, long long sC1, long long sC2,
         int K, int zdiv, float* __restrict__ Lv) {
    constexpr int BM = 128, BN = 128, BK = 32;
    constexpr int AKP = BK + 8;    // 40 halves/row (80 B)
    constexpr int BNP = BN + 8;    // 136 halves/row (272 B)
    constexpr int AS_SZ = BM * AKP;    // 5120 halves
    constexpr int BS_SZ = BK * BNP;    // 4352 halves
    constexpr int STG = AS_SZ + BS_SZ; // 9472 halves per stage
    extern __shared__ __align__(16) char smraw[];
    __half* smem = reinterpret_cast<__half*>(smraw);

    int z  = blockIdx.z;
    int z1 = z / zdiv, z2 = z - z1 * zdiv;
    A += (size_t)(z1 * sA1 + z2 * sA2);
    B += (size_t)(z1 * sB1 + z2 * sB2);
    C += (size_t)(z1 * sC1 + z2 * sC2);

    int tid = threadIdx.x;
    int wid = tid >> 5;
    int wm = wid & 1, wn = wid >> 1;          // 2x2 warps of 64x64
    int bm0 = blockIdx.y * BM, bn0 = blockIdx.x * BN;

    auto load_stage = [&](int kt, int s) {
        __half* As = smem + s * STG;
        __half* Bs = As + AS_SZ;
        #pragma unroll
        for (int it = 0; it < 4; it++) {      // A tile: 128 x 32 halves
            int idx = tid + it * 128;
            int r = idx >> 2, c = (idx & 3) << 3;
            cp_async16(&As[r * AKP + c],
                       A + (size_t)(bm0 + r) * lda + kt + c);
        }
        #pragma unroll
        for (int it = 0; it < 4; it++) {      // B tile: 32(k) x 128(n) halves
            int idx = tid + it * 128;
            int r = idx >> 4, c = (idx & 15) << 3;
            cp_async16(&Bs[r * BNP + c],
                       B + (size_t)(kt + r) * ldb + bn0 + c);
        }
    };

    wmma::fragment<wmma::accumulator, 16, 16, 16, float> acc[4][4];
    #pragma unroll
    for (int i = 0; i < 4; i++)
        #pragma unroll
        for (int j = 0; j < 4; j++) wmma::fill_fragment(acc[i][j], 0.0f);

    float lsum = 0.f;
    int T = K / BK;
    load_stage(0, 0);  cp_commit();
    load_stage(BK, 1); cp_commit();

    int sbuf = 0;       // stage of tile t (t % 3)
    for (int t = 0; t < T; t++) {
        cp_wait1();
        __syncthreads();
        int nt = t + 2;
        if (nt < T) {
            int ns = sbuf + 2; if (ns >= 3) ns -= 3;
            load_stage(nt * BK, ns);
            cp_commit();
        }
        __half* As = smem + sbuf * STG;
        __half* Bs = As + AS_SZ;
        if (SUMR) {                     // thread r sums row r (rotated access)
            const __half* ar = &As[tid * AKP];
            #pragma unroll
            for (int c = 0; c < BK; c++) lsum += __half2float(ar[(tid + c) & 31]);
        }
        #pragma unroll
        for (int ks = 0; ks < BK; ks += 16) {
            wmma::fragment<wmma::matrix_a, 16, 16, 16, __half, wmma::row_major> af[4];
            #pragma unroll
            for (int i = 0; i < 4; i++)
                wmma::load_matrix_sync(af[i], &As[(wm * 64 + i * 16) * AKP + ks], AKP);
            #pragma unroll
            for (int j = 0; j < 4; j++) {
                wmma::fragment<wmma::matrix_b, 16, 16, 16, __half, wmma::row_major> bf;
                wmma::load_matrix_sync(bf, &Bs[ks * BNP + wn * 64 + j * 16], BNP);
                #pragma unroll
                for (int i = 0; i < 4; i++)
                    wmma::mma_sync(acc[i][j], af[i], bf, acc[i][j]);
            }
        }
        if (++sbuf == 3) sbuf = 0;
    }
    if (SUMR)
        Lv[(size_t)z * S_ + bm0 + tid] = lsum;
    #pragma unroll
    for (int i = 0; i < 4; i++)
        #pragma unroll
        for (int j = 0; j < 4; j++)
            wmma::store_matrix_sync(C + (size_t)(bm0 + wm * 64 + i * 16) * ldc + bn0 + wn * 64 + j * 16,
                                    acc[i][j], ldc, wmma::mem_row_major);
}

static const int SMEM_G3H = 3 * (128*40 + 32*136) * 2;   // 56832 bytes

// ---------------- fp16 WMMA GEMM BT + exp epilogue (scores -> E, half) --------
// C[M,N](h) = exp(A[M,K](h) * B[N,K](h)^T - 2); 128x128 tile, 4 warps of 64x64.
__global__ void __launch_bounds__(128, 2)
k_gemmBTexp(const __half* __restrict__ A, int lda, long long sA1,
            const __half* __restrict__ B, int ldb, long long sB1,
            __half*       __restrict__ C, int ldc, long long sC1,
            int K) {
    constexpr int BM = 128, BN = 128, BK = 32;
    constexpr int AKP = BK + 8;        // 40 halves
    constexpr int AS_SZ = BM * AKP;    // 5120 halves
    extern __shared__ __align__(16) char smraw[];
    __half* sh = reinterpret_cast<__half*>(smraw);
    __half* As0 = sh;
    __half* As1 = sh + AS_SZ;
    __half* Bs0 = sh + 2 * AS_SZ;
    __half* Bs1 = sh + 3 * AS_SZ;
    float* scr = reinterpret_cast<float*>(smraw + 4 * AS_SZ * 2);  // 4 warps x 320 f32

    int z  = blockIdx.z;
    A += (size_t)z * sA1;
    B += (size_t)z * sB1;
    C += (size_t)z * sC1;

    int tid = threadIdx.x;
    int wid = tid >> 5, lane = tid & 31;
    int wm = wid & 1, wn = wid >> 1;
    int bm0 = blockIdx.y * BM, bn0 = blockIdx.x * BN;

    auto load_stage = [&](int kt, int buf) {
        __half* As = buf ? As1 : As0;
        __half* Bs = buf ? Bs1 : Bs0;
        #pragma unroll
        for (int it = 0; it < 4; it++) {
            int idx = tid + it * 128;
            int r = idx >> 2, c = (idx & 3) << 3;
            cp_async16(&As[r * AKP + c],
                       A + (size_t)(bm0 + r) * lda + kt + c);
        }
        #pragma unroll
        for (int it = 0; it < 4; it++) {
            int idx = tid + it * 128;
            int r = idx >> 2, c = (idx & 3) << 3;
            cp_async16(&Bs[r * AKP + c],
                       B + (size_t)(bn0 + r) * ldb + kt + c);
        }
    };

    wmma::fragment<wmma::accumulator, 16, 16, 16, float> acc[4][4];
    #pragma unroll
    for (int i = 0; i < 4; i++)
        #pragma unroll
        for (int j = 0; j < 4; j++) wmma::fill_fragment(acc[i][j], 0.0f);

    int T = K / BK;
    load_stage(0, 0);
    cp_commit();

    for (int t = 0; t < T; t++) {
        if (t + 1 < T) load_stage((t + 1) * BK, (t + 1) & 1);
        cp_commit();
        cp_wait1();
        __syncthreads();
        int buf = t & 1;
        __half* As = buf ? As1 : As0;
        __half* Bs = buf ? Bs1 : Bs0;
        #pragma unroll
        for (int ks = 0; ks < BK; ks += 16) {
            wmma::fragment<wmma::matrix_a, 16, 16, 16, __half, wmma::row_major> af[4];
            #pragma unroll
            for (int i = 0; i < 4; i++)
                wmma::load_matrix_sync(af[i], &As[(wm * 64 + i * 16) * AKP + ks], AKP);
            #pragma unroll
            for (int j = 0; j < 4; j++) {
                wmma::fragment<wmma::matrix_b, 16, 16, 16, __half, wmma::col_major> bf;
                wmma::load_matrix_sync(bf, &Bs[(wn * 64 + j * 16) * AKP + ks], AKP);
                #pragma unroll
                for (int i = 0; i < 4; i++)
                    wmma::mma_sync(acc[i][j], af[i], bf, acc[i][j]);
            }
        }
        __syncthreads();
    }

    // epilogue: per-warp smem staging, exp(x-2), half store
    float* scrw = scr + wid * 320;   // 16 x 20 f32
    int row = lane >> 1, ch = (lane & 1) * 8;
    #pragma unroll
    for (int i = 0; i < 4; i++)
        #pragma unroll
        for (int j = 0; j < 4; j++) {
            __syncwarp();
            wmma::store_matrix_sync(scrw, acc[i][j], 20, wmma::mem_row_major);
            __syncwarp();
            __align__(16) __half hv[8];
            #pragma unroll
            for (int e = 0; e < 8; e++)
                hv[e] = __float2half_rn(__expf(scrw[row * 20 + ch + e] - 2.0f));
            *reinterpret_cast<uint4*>(
                &C[(size_t)(bm0 + wm * 64 + i * 16 + row) * ldc + bn0 + wn * 64 + j * 16 + ch]) =
                *reinterpret_cast<uint4*>(hv);
        }
}

static const int SMEM_BTH = 4 * 5120 * 2 + 4 * 320 * 4;   // 40960 + 5120 = 46080

// ---------------- K4: qkv bias + RMSNorm + RoPE -> half [B,H,S,HD] ------------
__global__ void k_qkvpost(const float* __restrict__ qkv_b,
                          const float* __restrict__ cosb,
                          const float* __restrict__ sinb,
                          const float* __restrict__ nqw,
                          const float* __restrict__ nkw) {
    __shared__ float sh4[4];
    __shared__ float bufq[HD_], bufk[HD_];
    int tok = blockIdx.x, h = blockIdx.y, d = threadIdx.x;
    int b = tok >> 10, s = tok & 1023;
    size_t base = (size_t)tok * D3 + h * HD_;
    float qv = g_qkv[base + d]          + qkv_b[h * HD_ + d];
    float kv = g_qkv[base + D_ + d]     + qkv_b[D_ + h * HD_ + d];
    float vv = g_qkv[base + 2*D_ + d]   + qkv_b[2*D_ + h * HD_ + d];
    float sq = block_sum<4>(qv * qv, sh4);
    float sk = block_sum<4>(kv * kv, sh4);
    float rq = rsqrtf(sq * (1.f / HD_) + 1e-6f);
    float rk = rsqrtf(sk * (1.f / HD_) + 1e-6f);
    float qn = qv * rq * nqw[d];
    float kn = kv * rk * nkw[d];
    bufq[d] = qn; bufk[d] = kn;
    __syncthreads();
    float qo = qn, ko = kn;
    if (d < RD_) {
        int i = d >> 1;
        float c  = cosb[s * (RD_/2) + i];
        float sn = sinb[s * (RD_/2) + i];
        if ((d & 1) == 0) { qo = bufq[d] * c - bufq[d+1] * sn;
                            ko = bufk[d] * c - bufk[d+1] * sn; }
        else              { qo = bufq[d-1] * sn + bufq[d] * c;
                            ko = bufk[d-1] * sn + bufk[d] * c; }
    }
    size_t ob = ((size_t)(b * H_ + h) * S_ + s) * HD_ + d;
    g_qh[ob] = __float2half_rn(qo * 0.08838834764831845f);  // 1/sqrt(HD) in Q
    g_kh[ob] = __float2half_rn(ko);
    g_vh[ob] = __float2half_rn(vv);
}

// ---------------- K7: normalize O' by row sums -> half g_oh -------------------
__global__ void k_onorm() {
    size_t idx = ((size_t)blockIdx.x * blockDim.x + threadIdx.x) * 4;
    int n = (int)(idx & (D_ - 1));
    int m = (int)(idx >> 11);        // token
    int b = m >> 10, s = m & 1023;
    int h = n >> 7;
    float inv = 1.f / g_l[((size_t)(b * H_ + h)) * S_ + s];
    float4 v = *reinterpret_cast<float4*>(&g_t[idx]);
    __half2* o2 = reinterpret_cast<__half2*>(&g_oh[idx]);
    o2[0] = __floats2half2_rn(v.x * inv, v.y * inv);
    o2[1] = __floats2half2_rn(v.z * inv, v.w * inv);
}

// ---------------- K9: bias + gate + residual ----------------------------------
__global__ void k_final(const float* __restrict__ x,
                        const float* __restrict__ out_b,
                        float* __restrict__ out) {
    size_t idx = ((size_t)blockIdx.x * blockDim.x + threadIdx.x) * 4;
    int n = (int)(idx & (D_ - 1));
    int m = (int)(idx >> 11);
    int b = m >> 10;
    const float* gate = g_m3 + b * D3 + 2 * D_;
    float4 t  = *reinterpret_cast<float4*>(&g_t[idx]);
    float4 xr = *reinterpret_cast<const float4*>(&x[idx]);
    float4 o;
    o.x = (t.x + out_b[n+0]) * gate[n+0] + xr.x;
    o.y = (t.y + out_b[n+1]) * gate[n+1] + xr.y;
    o.z = (t.z + out_b[n+2]) * gate[n+2] + xr.z;
    o.w = (t.w + out_b[n+3]) * gate[n+3] + xr.w;
    *reinterpret_cast<float4*>(&out[idx]) = o;
}

// ---------------- launch ------------------------------------------------------
extern "C" void kernel_launch(void* const* d_in, const int* in_sizes, int n_in,
                              void* d_out, int out_size) {
    const float* x     = (const float*)d_in[0];
    const float* mod   = (const float*)d_in[1];
    const float* cosb  = (const float*)d_in[2];
    const float* sinb  = (const float*)d_in[3];
    const float* qkv_w = (const float*)d_in[4];
    const float* qkv_b = (const float*)d_in[5];
    const float* mod_w = (const float*)d_in[6];
    const float* mod_b = (const float*)d_in[7];
    const float* out_w = (const float*)d_in[8];
    const float* out_b = (const float*)d_in[9];
    const float* nqw   = (const float*)d_in[10];
    const float* nkw   = (const float*)d_in[11];
    float* out = (float*)d_out;

    __half *p_xnh, *p_qh, *p_kh, *p_vh, *p_sh, *p_oh, *p_qkvwh, *p_outwh;
    float *p_qkv, *p_l, *p_t;
    cudaGetSymbolAddress((void**)&p_xnh, g_xnh);
    cudaGetSymbolAddress((void**)&p_qkv, g_qkv);
    cudaGetSymbolAddress((void**)&p_qh, g_qh);
    cudaGetSymbolAddress((void**)&p_kh, g_kh);
    cudaGetSymbolAddress((void**)&p_vh, g_vh);
    cudaGetSymbolAddress((void**)&p_sh, g_sh);
    cudaGetSymbolAddress((void**)&p_l, g_l);
    cudaGetSymbolAddress((void**)&p_oh, g_oh);
    cudaGetSymbolAddress((void**)&p_t, g_t);
    cudaGetSymbolAddress((void**)&p_qkvwh, g_qkvwh);
    cudaGetSymbolAddress((void**)&p_outwh, g_outwh);

    cudaFuncSetAttribute(k_gemm3h<false>, cudaFuncAttributeMaxDynamicSharedMemorySize, SMEM_G3H);
    cudaFuncSetAttribute(k_gemm3h<true>,  cudaFuncAttributeMaxDynamicSharedMemorySize, SMEM_G3H);
    cudaFuncSetAttribute(k_gemmBTexp, cudaFuncAttributeMaxDynamicSharedMemorySize, SMEM_BTH);

    // 0) round the big weights to fp16 scratch
    k_round_h<<<(D_*D3)/(4*256), 256>>>(qkv_w, p_qkvwh);
    k_round_h<<<(D_*D_)/(4*256), 256>>>(out_w, p_outwh);
    // 1) m3 = mod @ mod_w + mod_b  (f32 path)
    k_mod_part<<<dim3(D3/128, KC), 128>>>(mod, mod_w);
    k_mod_red<<<(B_*D3)/256, 256>>>(mod_b);
    // 2) xn = modulate(layernorm(x)) -> fp16
    k_lnmod<<<NT, 256>>>(x);
    // 3) qkv = xn @ qkv_w  (fp16 GEMM, f32 out; bias folded into K4)
    k_gemm3h<false><<<dim3(D3/128, NT/128), 128, SMEM_G3H>>>(
        p_xnh, D_, 0, 0, p_qkvwh, D3, 0, 0, p_qkv, D3, 0, 0, D_, 1, nullptr);
    // 4) bias + rmsnorm + rope -> q,k,v fp16 [B,H,S,HD]
    k_qkvpost<<<dim3(NT, H_), HD_>>>(qkv_b, cosb, sinb, nqw, nkw);
    // 5) E = exp(Q @ K^T - 2) fp16 (bounded: |s|<=11.33 -> E<=1.2e4 < 65504)
    k_gemmBTexp<<<dim3(S_/128, S_/128, B_*H_), 128, SMEM_BTH>>>(
        p_qh, HD_, (long long)S_*HD_,
        p_kh, HD_, (long long)S_*HD_,
        p_sh, S_,  (long long)S_*S_, HD_);
    // 6) O' = E @ V (f32 out -> g_t); l[row] = sum E (full K per CTA)
    k_gemm3h<true><<<dim3(1, S_/128, B_*H_), 128, SMEM_G3H>>>(
        p_sh, S_,  (long long)H_*S_*S_,  (long long)S_*S_,
        p_vh, HD_, (long long)H_*S_*HD_, (long long)S_*HD_,
        p_t,  D_,  (long long)S_*D_,     (long long)HD_, S_, H_, p_l);
    // 7) O = fp16(O'/l)
    k_onorm<<<(NT*D_)/(4*256), 256>>>();
    // 8) t = O @ out_w  (fp16 GEMM, f32 out)
    k_gemm3h<false><<<dim3(D_/128, NT/128), 128, SMEM_G3H>>>(
        p_oh, D_, 0, 0, p_outwh, D_, 0, 0, p_t, D_, 0, 0, D_, 1, nullptr);
    // 9) out = (t + out_b) * gate + x
    k_final<<<(NT*D_)/(4*256), 256>>>(x, out_b, out);
}